// round 1
// baseline (speedup 1.0000x reference)
#include <cuda_runtime.h>
#include <cstdint>

// Problem constants
#define Bb 4
#define Ll 4096
#define Dd 2048
#define Hh 8
#define BLt (Bb*Ll)          // 16384 tokens
#define BD  (Bb*Dd)          // 8192 channels
#define CHUNKS 16
#define CLEN (Ll/CHUNKS)     // 256

// Scratch: interleaved (a, normalized_x) pairs, plus chunk-scan state.
__device__ float2 g_anx[(size_t)BLt * Dd];          // 268 MB
__device__ float  g_chunkA[CHUNKS * BD];
__device__ float  g_chunkH[CHUNKS * BD];
__device__ float  g_Hin[CHUNKS * BD];

__device__ __forceinline__ uint32_t f2tf(float f) {
    uint32_t u;
    asm("cvt.rna.tf32.f32 %0, %1;" : "=r"(u) : "f"(f));
    return u;
}

__device__ __forceinline__ void mma_tf32(float c[4], const uint32_t a[4], const uint32_t b[2]) {
    asm volatile(
        "mma.sync.aligned.m16n8k8.row.col.f32.tf32.tf32.f32 "
        "{%0,%1,%2,%3}, {%4,%5,%6,%7}, {%8,%9}, {%0,%1,%2,%3};"
        : "+f"(c[0]), "+f"(c[1]), "+f"(c[2]), "+f"(c[3])
        : "r"(a[0]), "r"(a[1]), "r"(a[2]), "r"(a[3]), "r"(b[0]), "r"(b[1]));
}

// ---------------------------------------------------------------------------
// Kernel A: block-diag gate GEMMs (tf32 mma) + fused elementwise.
// Block = 128 tokens x (64 j-cols x 2 gates) of one head.
// 8 warps: (mWarp 0..1) x (gate 0..1) x (jWarp 0..1); warp tile 64x32.
// ---------------------------------------------------------------------------
__global__ __launch_bounds__(256, 2)
void gates_kernel(const float* __restrict__ x,
                  const float* __restrict__ a_param,
                  const float* __restrict__ ig_w, const float* __restrict__ ig_b,
                  const float* __restrict__ ag_w, const float* __restrict__ ag_b)
{
    __shared__ float smem[8448];          // union: As[128][33] + Bs[2][32][66]  OR  stage[64][130]
    float* As = smem;                     // 4224 floats
    float* Bs = smem + 4224;              // 4224 floats

    const int tid  = threadIdx.x;
    const int warp = tid >> 5, lane = tid & 31;
    const int grp  = lane >> 2, lq = lane & 3;
    const int head = blockIdx.x >> 2;
    const int jb   = blockIdx.x & 3;      // 64-col slab within head
    const int m0   = blockIdx.y * 128;    // token base
    const int mW    = warp >> 2;          // 0..1 (64-token half)
    const int gateW = (warp >> 1) & 1;    // 0 = input gate, 1 = a gate
    const int jW    = warp & 1;           // 0..1 (32-col half of slab)

    float c[4][4][4];
    #pragma unroll
    for (int i = 0; i < 4; ++i)
        #pragma unroll
        for (int j = 0; j < 4; ++j)
            #pragma unroll
            for (int k = 0; k < 4; ++k) c[i][j][k] = 0.f;

    #pragma unroll 1
    for (int kt = 0; kt < 8; ++kt) {
        // Load A tile: 128 tokens x 32 K (this head's slice), convert to tf32
        #pragma unroll
        for (int i = 0; i < 4; ++i) {
            int idx = tid + i * 256;               // 0..1023
            int r = idx >> 3, k4 = idx & 7;
            const float4 v = *(const float4*)(x + (size_t)(m0 + r) * Dd + head * 256 + kt * 32 + k4 * 4);
            float* dst = As + r * 33 + k4 * 4;
            dst[0] = __uint_as_float(f2tf(v.x));
            dst[1] = __uint_as_float(f2tf(v.y));
            dst[2] = __uint_as_float(f2tf(v.z));
            dst[3] = __uint_as_float(f2tf(v.w));
        }
        // Load B tiles for both gates: 32 K x 64 j each
        #pragma unroll
        for (int i = 0; i < 4; ++i) {
            int idx = tid + i * 256;               // 0..1023
            int g = idx >> 9;                      // 0..1
            int rem = idx & 511;
            int k = rem >> 4, j4 = rem & 15;
            const float* wsrc = g ? ag_w : ig_w;
            const float4 v = *(const float4*)(wsrc + head * 65536 + (kt * 32 + k) * 256 + jb * 64 + j4 * 4);
            float* dst = Bs + g * 2112 + k * 66 + j4 * 4;
            dst[0] = __uint_as_float(f2tf(v.x));
            dst[1] = __uint_as_float(f2tf(v.y));
            dst[2] = __uint_as_float(f2tf(v.z));
            dst[3] = __uint_as_float(f2tf(v.w));
        }
        __syncthreads();

        #pragma unroll
        for (int k8 = 0; k8 < 4; ++k8) {
            uint32_t afr[4][4];
            #pragma unroll
            for (int mt = 0; mt < 4; ++mt) {
                const float* ap = As + (mW * 64 + mt * 16 + grp) * 33 + k8 * 8 + lq;
                afr[mt][0] = __float_as_uint(ap[0]);
                afr[mt][1] = __float_as_uint(ap[8 * 33]);
                afr[mt][2] = __float_as_uint(ap[4]);
                afr[mt][3] = __float_as_uint(ap[8 * 33 + 4]);
            }
            uint32_t bfr[4][2];
            #pragma unroll
            for (int nt = 0; nt < 4; ++nt) {
                const float* bp = Bs + gateW * 2112 + (k8 * 8 + lq) * 66 + jW * 32 + nt * 8 + grp;
                bfr[nt][0] = __float_as_uint(bp[0]);
                bfr[nt][1] = __float_as_uint(bp[4 * 66]);
            }
            #pragma unroll
            for (int mt = 0; mt < 4; ++mt)
                #pragma unroll
                for (int nt = 0; nt < 4; ++nt)
                    mma_tf32(c[mt][nt], afr[mt], bfr[nt]);
        }
        __syncthreads();
    }

    // Epilogue: stage z for both gates in smem (two 64-token halves), then
    // fused elementwise -> write (a, nx) pairs.
    float* stage = smem;                  // [64][130]: col = jLocal*2 + gate
    #pragma unroll 1
    for (int half = 0; half < 2; ++half) {
        if (mW == half) {
            #pragma unroll
            for (int mt = 0; mt < 4; ++mt) {
                #pragma unroll
                for (int nt = 0; nt < 4; ++nt) {
                    int r0 = mt * 16 + grp;
                    int cb = (jW * 32 + nt * 8 + lq * 2) * 2 + gateW;
                    stage[r0 * 130 + cb]             = c[mt][nt][0];
                    stage[r0 * 130 + cb + 2]         = c[mt][nt][1];
                    stage[(r0 + 8) * 130 + cb]       = c[mt][nt][2];
                    stage[(r0 + 8) * 130 + cb + 2]   = c[mt][nt][3];
                }
            }
        }
        __syncthreads();
        #pragma unroll 4
        for (int idx = tid; idx < 64 * 64; idx += 256) {
            int r  = idx >> 6;
            int jL = idx & 63;
            int t  = m0 + half * 64 + r;
            int d  = head * 256 + jb * 64 + jL;
            float zi = stage[r * 130 + jL * 2]     + ig_b[d];
            float za = stage[r * 130 + jL * 2 + 1] + ag_b[d];
            float xv = x[(size_t)t * Dd + d];
            float gx = 1.f / (1.f + expf(-zi));
            float ga = 1.f / (1.f + expf(-za));
            float sp = log1pf(expf(a_param[d]));
            float la = -8.f * ga * sp;
            float a  = expf(la);
            float m2 = 1.f - expf(2.f * la);
            float mult = sqrtf(fmaxf(m2, 0.f));
            g_anx[(size_t)t * Dd + d] = make_float2(a, xv * gx * mult);
        }
        __syncthreads();
    }
}

// ---------------------------------------------------------------------------
// Scan phase: blocked scan over L in CHUNKS chunks of CLEN.
// ---------------------------------------------------------------------------
__global__ void scan_part1()   // per-(channel, chunk): A-product and h_end (h0 = 0)
{
    int g  = blockIdx.x * blockDim.x + threadIdx.x;   // BD*CHUNKS threads
    int ci = g / BD;
    int ch = g % BD;
    int b = ch / Dd, d = ch % Dd;
    const float2* p = g_anx + ((size_t)(b * Ll + ci * CLEN)) * Dd + d;

    float h = 0.f, A = 1.f;
    float2 cur[8];
    #pragma unroll
    for (int i = 0; i < 8; ++i) cur[i] = p[(size_t)i * Dd];
    #pragma unroll 1
    for (int base = 0; base < CLEN; base += 8) {
        float2 nxt[8];
        if (base + 8 < CLEN) {
            #pragma unroll
            for (int i = 0; i < 8; ++i) nxt[i] = p[(size_t)(base + 8 + i) * Dd];
        } else {
            #pragma unroll
            for (int i = 0; i < 8; ++i) nxt[i] = make_float2(0.f, 0.f);
        }
        #pragma unroll
        for (int i = 0; i < 8; ++i) {
            h = fmaf(cur[i].x, h, cur[i].y);
            A *= cur[i].x;
        }
        #pragma unroll
        for (int i = 0; i < 8; ++i) cur[i] = nxt[i];
    }
    g_chunkA[ci * BD + ch] = A;
    g_chunkH[ci * BD + ch] = h;
}

__global__ void scan_part2(const float* __restrict__ hidden, float* __restrict__ hfinal, int write_h)
{
    int ch = blockIdx.x * blockDim.x + threadIdx.x;   // BD threads
    float h = hidden[ch];
    #pragma unroll
    for (int ci = 0; ci < CHUNKS; ++ci) {
        g_Hin[ci * BD + ch] = h;
        h = fmaf(g_chunkA[ci * BD + ch], h, g_chunkH[ci * BD + ch]);
    }
    if (write_h) hfinal[ch] = h;
}

__global__ void scan_part3(float* __restrict__ y)   // final scan with correct chunk-initial h
{
    int g  = blockIdx.x * blockDim.x + threadIdx.x;
    int ci = g / BD;
    int ch = g % BD;
    int b = ch / Dd, d = ch % Dd;
    size_t off = ((size_t)(b * Ll + ci * CLEN)) * Dd + d;
    const float2* p = g_anx + off;
    float* yp = y + off;

    float h = g_Hin[ci * BD + ch];
    float2 cur[8];
    #pragma unroll
    for (int i = 0; i < 8; ++i) cur[i] = p[(size_t)i * Dd];
    #pragma unroll 1
    for (int base = 0; base < CLEN; base += 8) {
        float2 nxt[8];
        if (base + 8 < CLEN) {
            #pragma unroll
            for (int i = 0; i < 8; ++i) nxt[i] = p[(size_t)(base + 8 + i) * Dd];
        } else {
            #pragma unroll
            for (int i = 0; i < 8; ++i) nxt[i] = make_float2(0.f, 0.f);
        }
        #pragma unroll
        for (int i = 0; i < 8; ++i) {
            h = fmaf(cur[i].x, h, cur[i].y);
            yp[(size_t)(base + i) * Dd] = h;
        }
        #pragma unroll
        for (int i = 0; i < 8; ++i) cur[i] = nxt[i];
    }
}

extern "C" void kernel_launch(void* const* d_in, const int* in_sizes, int n_in,
                              void* d_out, int out_size)
{
    const float* x        = (const float*)d_in[0];
    const float* hidden   = (const float*)d_in[1];
    const float* a_param  = (const float*)d_in[2];
    const float* ig_w     = (const float*)d_in[3];
    const float* ig_b     = (const float*)d_in[4];
    const float* ag_w     = (const float*)d_in[5];
    const float* ag_b     = (const float*)d_in[6];
    float* y = (float*)d_out;

    int write_h = (out_size >= BLt * Dd + BD) ? 1 : 0;
    float* hf = y + (size_t)BLt * Dd;

    dim3 gA(32, 128);   // x: head*4 + j-slab (fast -> x-tile reuse in L2), y: token tiles
    gates_kernel<<<gA, 256>>>(x, a_param, ig_w, ig_b, ag_w, ag_b);
    scan_part1<<<(BD * CHUNKS) / 256, 256>>>();
    scan_part2<<<BD / 256, 256>>>(hidden, hf, write_h);
    scan_part3<<<(BD * CHUNKS) / 256, 256>>>(y);
}

// round 3
// speedup vs baseline: 2.7589x; 2.7589x over previous
#include <cuda_runtime.h>
#include <cstdint>

// Problem constants
#define Bb 4
#define Ll 4096
#define Dd 2048
#define Hh 8
#define BLt (Bb*Ll)          // 16384 tokens
#define BD  (Bb*Dd)          // 8192 channels
#define CHUNKS 32
#define CLEN (Ll/CHUNKS)     // 128

// Scratch
__device__ float2 g_anx[(size_t)BLt * Dd];          // 268 MB
__device__ float  g_wT[16 * 256 * 256];             // [head][gate*256+j][k] K-major, 4 MB
__device__ float  g_sp[Dd];                         // softplus(a_param)
__device__ float  g_chunkA[CHUNKS * BD];
__device__ float  g_chunkH[CHUNKS * BD];
__device__ float  g_Hin[CHUNKS * BD];

__device__ __forceinline__ uint32_t smem_u32(const void* p) {
    uint32_t a;
    asm("{ .reg .u64 t; cvta.to.shared.u64 t, %1; cvt.u32.u64 %0, t; }" : "=r"(a) : "l"(p));
    return a;
}
#define SWZ128(o) ((o) ^ (((o) >> 3) & 0x70))

__device__ __forceinline__ void cp16(uint32_t saddr, const void* g) {
    asm volatile("cp.async.cg.shared.global [%0], [%1], 16;" :: "r"(saddr), "l"(g));
}

__device__ __forceinline__ void ldsm4(uint32_t* r, uint32_t addr) {
    asm volatile("ldmatrix.sync.aligned.m8n8.x4.shared.b16 {%0,%1,%2,%3}, [%4];"
        : "=r"(r[0]), "=r"(r[1]), "=r"(r[2]), "=r"(r[3]) : "r"(addr));
}

__device__ __forceinline__ void mma_tf32(float c[4], const uint32_t a[4], const uint32_t* b) {
    asm volatile(
        "mma.sync.aligned.m16n8k8.row.col.f32.tf32.tf32.f32 "
        "{%0,%1,%2,%3}, {%4,%5,%6,%7}, {%8,%9}, {%0,%1,%2,%3};"
        : "+f"(c[0]), "+f"(c[1]), "+f"(c[2]), "+f"(c[3])
        : "r"(a[0]), "r"(a[1]), "r"(a[2]), "r"(a[3]), "r"(b[0]), "r"(b[1]));
}

// ---------------------------------------------------------------------------
// Prep: transpose weights to K-major [h][gate*256+j][k]; precompute softplus.
// ---------------------------------------------------------------------------
__global__ void prep_kernel(const float* __restrict__ ig_w, const float* __restrict__ ag_w,
                            const float* __restrict__ a_param)
{
    __shared__ float t[32][33];
    int bid = blockIdx.x;
    int mat = bid >> 6;                // head*2 + gate
    int tile = bid & 63;
    int tj = tile & 7, tk = tile >> 3;
    int head = mat >> 1, gate = mat & 1;
    const float* w = (gate ? ag_w : ig_w) + head * 65536;
    int tx = threadIdx.x & 31, ty = threadIdx.x >> 5;   // 32 x 8

    #pragma unroll
    for (int r = 0; r < 4; ++r)
        t[ty + r * 8][tx] = w[(tk * 32 + ty + r * 8) * 256 + tj * 32 + tx];
    __syncthreads();
    #pragma unroll
    for (int r = 0; r < 4; ++r) {
        int j = tj * 32 + ty + r * 8;
        g_wT[(size_t)(head * 512 + gate * 256 + j) * 256 + tk * 32 + tx] = t[tx][ty + r * 8];
    }
    if (bid == 0) {
        for (int d = threadIdx.x; d < Dd; d += 256)
            g_sp[d] = log1pf(__expf(a_param[d]));
    }
}

// ---------------------------------------------------------------------------
// Gates: legacy tf32 mma (ldmatrix + cp.async double buffer) + fused epilogue.
// Block: 128 tokens x (64 j x 2 gates). 8 warps (2m x 4n), warp tile 64x32.
// ---------------------------------------------------------------------------
#define OFF_B0 32768
#define SMEM_TOTAL 67584   // max(compute: 2*16K A + 2*16K B, epilogue: 2*128*66*4)

__global__ __launch_bounds__(256, 2)
void gates_kernel(const float* __restrict__ x,
                  const float* __restrict__ ig_b, const float* __restrict__ ag_b)
{
    extern __shared__ char smem[];
    const uint32_t sb = smem_u32(smem);
    const int tid  = threadIdx.x;
    const int warp = tid >> 5, lane = tid & 31;
    const int grp = lane >> 2, lq = lane & 3;
    const int head  = blockIdx.x >> 2;
    const int jslab = blockIdx.x & 3;      // 64 j-cols per slab
    const int m0    = blockIdx.y * 128;
    const int warpM = warp >> 2;           // 0..1
    const int warpN = warp & 3;            // 0..3 : gate = warpN>>1, njb = (warpN&1)*32

    // ldmatrix lane addressing
    const int seg = lane >> 3, r8 = lane & 7;
    const int aRow = warpM * 64 + (seg & 1) * 8 + r8;
    const int aKb  = (seg >> 1) * 16;
    const int bRow = warpN * 32 + (seg >> 1) * 8 + r8;
    const int bKb  = (seg & 1) * 16;

    float c[4][4][4];
    #pragma unroll
    for (int i = 0; i < 4; ++i)
        #pragma unroll
        for (int j = 0; j < 4; ++j)
            #pragma unroll
            for (int k = 0; k < 4; ++k) c[i][j][k] = 0.f;

    const float* xbase = x + (size_t)m0 * Dd + head * 256;
    const float* wbase = g_wT + (size_t)head * 512 * 256;

    auto load_stage = [&](int st, int kt) {
        uint32_t ab = sb + st * 16384;
        #pragma unroll
        for (int i = 0; i < 4; ++i) {
            int idx = tid + i * 256;            // 0..1023
            int r = idx >> 3, c16 = idx & 7;
            cp16(ab + SWZ128(r * 128 + c16 * 16), xbase + (size_t)r * Dd + kt * 32 + c16 * 4);
        }
        uint32_t bb = sb + OFF_B0 + st * 16384;
        #pragma unroll
        for (int i = 0; i < 4; ++i) {
            int idx = tid + i * 256;            // 0..1023
            int n = idx >> 3, c16 = idx & 7;
            int wrow = (n >> 6) * 256 + jslab * 64 + (n & 63);
            cp16(bb + SWZ128(n * 128 + c16 * 16), wbase + (size_t)wrow * 256 + kt * 32 + c16 * 4);
        }
        asm volatile("cp.async.commit_group;");
    };

    load_stage(0, 0);
    load_stage(1, 1);

    #pragma unroll 1
    for (int kt = 0; kt < 8; ++kt) {
        int st = kt & 1;
        if (kt < 7) asm volatile("cp.async.wait_group 1;");
        else        asm volatile("cp.async.wait_group 0;");
        __syncthreads();

        uint32_t sA = sb + st * 16384;
        uint32_t sB = sb + OFF_B0 + st * 16384;
        #pragma unroll
        for (int k8 = 0; k8 < 4; ++k8) {
            uint32_t a[4][4], b[2][4];
            #pragma unroll
            for (int mt = 0; mt < 4; ++mt)
                ldsm4(a[mt], sA + SWZ128((uint32_t)((aRow + mt * 16) * 128 + k8 * 32 + aKb)));
            #pragma unroll
            for (int np = 0; np < 2; ++np)
                ldsm4(b[np], sB + SWZ128((uint32_t)((bRow + np * 16) * 128 + k8 * 32 + bKb)));
            #pragma unroll
            for (int mt = 0; mt < 4; ++mt)
                #pragma unroll
                for (int nt = 0; nt < 4; ++nt)
                    mma_tf32(c[mt][nt], a[mt], &b[nt >> 1][(nt & 1) * 2]);
        }
        __syncthreads();
        if (kt + 2 < 8) load_stage(st, kt + 2);
    }

    // Stage z for both gates: zstage[gate][128 rows][66]
    {
        int gate = warpN >> 1;
        int njb  = (warpN & 1) * 32;
        #pragma unroll
        for (int mt = 0; mt < 4; ++mt) {
            #pragma unroll
            for (int nt = 0; nt < 4; ++nt) {
                int row = warpM * 64 + mt * 16 + grp;
                int j   = njb + nt * 8 + 2 * lq;
                float2* z0 = (float2*)(smem + ((gate * 128 + row) * 66 + j) * 4);
                float2* z1 = (float2*)(smem + ((gate * 128 + row + 8) * 66 + j) * 4);
                *z0 = make_float2(c[mt][nt][0], c[mt][nt][1]);
                *z1 = make_float2(c[mt][nt][2], c[mt][nt][3]);
            }
        }
    }
    __syncthreads();

    // Fused elementwise
    {
        const int j0 = tid & 63;
        const int d  = head * 256 + jslab * 64 + j0;
        const float bi = __ldg(ig_b + d);
        const float ba = __ldg(ag_b + d);
        const float sp = g_sp[d];
        const float L2E = 1.44269504088896f;
        const float* zs = (const float*)smem;
        #pragma unroll 4
        for (int it = 0; it < 32; ++it) {
            int row = (tid >> 6) + it * 4;
            float zi = zs[row * 66 + j0] + bi;
            float za = zs[(128 + row) * 66 + j0] + ba;
            float ei, ea, gx, ga, a, mult;
            asm("ex2.approx.f32 %0, %1;" : "=f"(ei) : "f"(-zi * L2E));
            asm("rcp.approx.f32 %0, %1;" : "=f"(gx) : "f"(1.f + ei));
            asm("ex2.approx.f32 %0, %1;" : "=f"(ea) : "f"(-za * L2E));
            asm("rcp.approx.f32 %0, %1;" : "=f"(ga) : "f"(1.f + ea));
            float la = -8.f * ga * sp;
            asm("ex2.approx.f32 %0, %1;" : "=f"(a) : "f"(la * L2E));
            float m2 = fmaxf(fmaf(-a, a, 1.f), 0.f);
            asm("sqrt.approx.f32 %0, %1;" : "=f"(mult) : "f"(m2));
            size_t off = (size_t)(m0 + row) * Dd + d;
            float xv = __ldg(x + off);
            g_anx[off] = make_float2(a, xv * gx * mult);
        }
    }
}

// ---------------------------------------------------------------------------
// Scan phase
// ---------------------------------------------------------------------------
__global__ void scan_part1()
{
    int g  = blockIdx.x * blockDim.x + threadIdx.x;
    int ci = g / BD;
    int ch = g % BD;
    int b = ch / Dd, d = ch % Dd;
    const float2* p = g_anx + ((size_t)(b * Ll + ci * CLEN)) * Dd + d;

    float h = 0.f, A = 1.f;
    float2 cur[8];
    #pragma unroll
    for (int i = 0; i < 8; ++i) cur[i] = p[(size_t)i * Dd];
    #pragma unroll 1
    for (int base = 0; base < CLEN; base += 8) {
        float2 nxt[8];
        if (base + 8 < CLEN) {
            #pragma unroll
            for (int i = 0; i < 8; ++i) nxt[i] = p[(size_t)(base + 8 + i) * Dd];
        } else {
            #pragma unroll
            for (int i = 0; i < 8; ++i) nxt[i] = make_float2(0.f, 0.f);
        }
        #pragma unroll
        for (int i = 0; i < 8; ++i) {
            h = fmaf(cur[i].x, h, cur[i].y);
            A *= cur[i].x;
        }
        #pragma unroll
        for (int i = 0; i < 8; ++i) cur[i] = nxt[i];
    }
    g_chunkA[ci * BD + ch] = A;
    g_chunkH[ci * BD + ch] = h;
}

__global__ void scan_part2(const float* __restrict__ hidden, float* __restrict__ hfinal, int write_h)
{
    int ch = blockIdx.x * blockDim.x + threadIdx.x;
    float h = hidden[ch];
    #pragma unroll
    for (int ci = 0; ci < CHUNKS; ++ci) {
        g_Hin[ci * BD + ch] = h;
        h = fmaf(g_chunkA[ci * BD + ch], h, g_chunkH[ci * BD + ch]);
    }
    if (write_h) hfinal[ch] = h;
}

__global__ void scan_part3(float* __restrict__ y)
{
    int g  = blockIdx.x * blockDim.x + threadIdx.x;
    int ci = g / BD;
    int ch = g % BD;
    int b = ch / Dd, d = ch % Dd;
    size_t off = ((size_t)(b * Ll + ci * CLEN)) * Dd + d;
    const float2* p = g_anx + off;
    float* yp = y + off;

    float h = g_Hin[ci * BD + ch];
    float2 cur[8];
    #pragma unroll
    for (int i = 0; i < 8; ++i) cur[i] = p[(size_t)i * Dd];
    #pragma unroll 1
    for (int base = 0; base < CLEN; base += 8) {
        float2 nxt[8];
        if (base + 8 < CLEN) {
            #pragma unroll
            for (int i = 0; i < 8; ++i) nxt[i] = p[(size_t)(base + 8 + i) * Dd];
        } else {
            #pragma unroll
            for (int i = 0; i < 8; ++i) nxt[i] = make_float2(0.f, 0.f);
        }
        #pragma unroll
        for (int i = 0; i < 8; ++i) {
            h = fmaf(cur[i].x, h, cur[i].y);
            yp[(size_t)(base + i) * Dd] = h;
        }
        #pragma unroll
        for (int i = 0; i < 8; ++i) cur[i] = nxt[i];
    }
}

extern "C" void kernel_launch(void* const* d_in, const int* in_sizes, int n_in,
                              void* d_out, int out_size)
{
    const float* x        = (const float*)d_in[0];
    const float* hidden   = (const float*)d_in[1];
    const float* a_param  = (const float*)d_in[2];
    const float* ig_w     = (const float*)d_in[3];
    const float* ig_b     = (const float*)d_in[4];
    const float* ag_w     = (const float*)d_in[5];
    const float* ag_b     = (const float*)d_in[6];
    float* y = (float*)d_out;

    int write_h = (out_size >= BLt * Dd + BD) ? 1 : 0;
    float* hf = y + (size_t)BLt * Dd;

    static int configured = 0;
    cudaFuncSetAttribute(gates_kernel, cudaFuncAttributeMaxDynamicSharedMemorySize, SMEM_TOTAL);
    (void)configured;

    prep_kernel<<<1024, 256>>>(ig_w, ag_w, a_param);
    gates_kernel<<<dim3(32, 128), 256, SMEM_TOTAL>>>(x, ig_b, ag_b);
    scan_part1<<<(BD * CHUNKS) / 256, 256>>>();
    scan_part2<<<BD / 256, 256>>>(hidden, hf, write_h);
    scan_part3<<<(BD * CHUNKS) / 256, 256>>>(y);
}

// round 5
// speedup vs baseline: 3.2140x; 1.1649x over previous
#include <cuda_runtime.h>
#include <cuda_fp16.h>
#include <cstdint>

// Problem constants
#define Bb 4
#define Ll 4096
#define Dd 2048
#define Hh 8
#define BLt (Bb*Ll)          // 16384 tokens
#define BD  (Bb*Dd)          // 8192 channels
#define CHUNKS 32
#define CLEN (Ll/CHUNKS)     // 128

// Scratch
__device__ float2 g_anx[(size_t)BLt * Dd];          // 268 MB
__device__ __half g_xh[(size_t)BLt * Dd];           // 67 MB, fp16 copy of x
__device__ __half g_wTh[16 * 256 * 256];            // [head][gate*256+j][k] K-major fp16
__device__ float  g_sp[Dd];                         // softplus(a_param)
__device__ float  g_chunkA[CHUNKS * BD];
__device__ float  g_chunkH[CHUNKS * BD];
__device__ float  g_Hin[CHUNKS * BD];

__device__ __forceinline__ uint32_t smem_u32(const void* p) {
    uint32_t a;
    asm("{ .reg .u64 t; cvta.to.shared.u64 t, %1; cvt.u32.u64 %0, t; }" : "=r"(a) : "l"(p));
    return a;
}
#define SWZ128(o) ((o) ^ (((o) >> 3) & 0x70))

__device__ __forceinline__ uint32_t h2u(__half2 h) {
    union { __half2 h; uint32_t u; } cvt;
    cvt.h = h;
    return cvt.u;
}

__device__ __forceinline__ void cp16(uint32_t saddr, const void* g) {
    asm volatile("cp.async.cg.shared.global [%0], [%1], 16;" :: "r"(saddr), "l"(g));
}

__device__ __forceinline__ void ldsm4(uint32_t* r, uint32_t addr) {
    asm volatile("ldmatrix.sync.aligned.m8n8.x4.shared.b16 {%0,%1,%2,%3}, [%4];"
        : "=r"(r[0]), "=r"(r[1]), "=r"(r[2]), "=r"(r[3]) : "r"(addr));
}

__device__ __forceinline__ void mma_f16(float c[4], const uint32_t a[4], uint32_t b0, uint32_t b1) {
    asm volatile(
        "mma.sync.aligned.m16n8k16.row.col.f32.f16.f16.f32 "
        "{%0,%1,%2,%3}, {%4,%5,%6,%7}, {%8,%9}, {%0,%1,%2,%3};"
        : "+f"(c[0]), "+f"(c[1]), "+f"(c[2]), "+f"(c[3])
        : "r"(a[0]), "r"(a[1]), "r"(a[2]), "r"(a[3]), "r"(b0), "r"(b1));
}

// ---------------------------------------------------------------------------
// xconv: fp32 x -> fp16 copy (one pass)
// ---------------------------------------------------------------------------
__global__ void xconv_kernel(const float* __restrict__ x)
{
    size_t i = ((size_t)blockIdx.x * 256 + threadIdx.x) * 8;
    float4 v0 = *(const float4*)(x + i);
    float4 v1 = *(const float4*)(x + i + 4);
    uint4 o;
    o.x = h2u(__floats2half2_rn(v0.x, v0.y));
    o.y = h2u(__floats2half2_rn(v0.z, v0.w));
    o.z = h2u(__floats2half2_rn(v1.x, v1.y));
    o.w = h2u(__floats2half2_rn(v1.z, v1.w));
    *(uint4*)(g_xh + i) = o;
}

// ---------------------------------------------------------------------------
// Prep: transpose weights to K-major fp16 [h][gate*256+j][k]; softplus.
// ---------------------------------------------------------------------------
__global__ void prep_kernel(const float* __restrict__ ig_w, const float* __restrict__ ag_w,
                            const float* __restrict__ a_param)
{
    __shared__ float t[32][33];
    int bid = blockIdx.x;
    int mat = bid >> 6;                // head*2 + gate
    int tile = bid & 63;
    int tj = tile & 7, tk = tile >> 3;
    int head = mat >> 1, gate = mat & 1;
    const float* w = (gate ? ag_w : ig_w) + head * 65536;
    int tx = threadIdx.x & 31, ty = threadIdx.x >> 5;   // 32 x 8

    #pragma unroll
    for (int r = 0; r < 4; ++r)
        t[ty + r * 8][tx] = w[(tk * 32 + ty + r * 8) * 256 + tj * 32 + tx];
    __syncthreads();
    #pragma unroll
    for (int r = 0; r < 4; ++r) {
        int j = tj * 32 + ty + r * 8;
        g_wTh[(size_t)(head * 512 + gate * 256 + j) * 256 + tk * 32 + tx] = __float2half(t[tx][ty + r * 8]);
    }
    if (bid == 0) {
        for (int d = threadIdx.x; d < Dd; d += 256)
            g_sp[d] = log1pf(__expf(a_param[d]));
    }
}

// ---------------------------------------------------------------------------
// Gates: fp16 mma (ldmatrix + cp.async double buffer) + fused epilogue that
// also produces the per-chunk scan summaries (chunkA, chunkH).
// Block: 128 tokens x (64 j x 2 gates). 8 warps (2m x 4n), warp tile 64x32.
// K chunk = 64 fp16 = 128B rows, 4 kt iterations.
// ---------------------------------------------------------------------------
#define OFF_B0 32768
#define OFF_SEG 67584
#define SMEM_TOTAL 69632

__global__ __launch_bounds__(256, 2)
void gates_kernel(const float* __restrict__ ig_b, const float* __restrict__ ag_b)
{
    extern __shared__ char smem[];
    const uint32_t sb = smem_u32(smem);
    const int tid  = threadIdx.x;
    const int warp = tid >> 5, lane = tid & 31;
    const int grp = lane >> 2, lq = lane & 3;
    const int head  = blockIdx.x >> 2;
    const int jslab = blockIdx.x & 3;      // 64 j-cols per slab
    const int m0    = blockIdx.y * 128;
    const int warpM = warp >> 2;           // 0..1
    const int warpN = warp & 3;            // 0..3 : gate = warpN>>1, njb = (warpN&1)*32

    const int lr = lane & 15, lc = (lane >> 4) * 16;

    float c[4][4][4];
    #pragma unroll
    for (int i = 0; i < 4; ++i)
        #pragma unroll
        for (int j = 0; j < 4; ++j)
            #pragma unroll
            for (int k = 0; k < 4; ++k) c[i][j][k] = 0.f;

    const __half* xbase = g_xh + (size_t)m0 * Dd + head * 256;
    const __half* wbase = g_wTh + (size_t)head * 512 * 256;

    auto load_stage = [&](int st, int kt) {
        uint32_t ab = sb + st * 16384;
        #pragma unroll
        for (int i = 0; i < 4; ++i) {
            int idx = tid + i * 256;            // 0..1023
            int r = idx >> 3, c16 = idx & 7;
            cp16(ab + SWZ128(r * 128 + c16 * 16), xbase + (size_t)r * Dd + kt * 64 + c16 * 8);
        }
        uint32_t bb = sb + OFF_B0 + st * 16384;
        #pragma unroll
        for (int i = 0; i < 4; ++i) {
            int idx = tid + i * 256;            // 0..1023
            int n = idx >> 3, c16 = idx & 7;
            int wrow = (n >> 6) * 256 + jslab * 64 + (n & 63);
            cp16(bb + SWZ128(n * 128 + c16 * 16), wbase + (size_t)wrow * 256 + kt * 64 + c16 * 8);
        }
        asm volatile("cp.async.commit_group;");
    };

    load_stage(0, 0);
    load_stage(1, 1);

    #pragma unroll 1
    for (int kt = 0; kt < 4; ++kt) {
        int st = kt & 1;
        if (kt < 3) asm volatile("cp.async.wait_group 1;");
        else        asm volatile("cp.async.wait_group 0;");
        __syncthreads();

        uint32_t sA = sb + st * 16384;
        uint32_t sB = sb + OFF_B0 + st * 16384;
        #pragma unroll
        for (int k16 = 0; k16 < 4; ++k16) {
            uint32_t a[4][4], b[2][4];
            #pragma unroll
            for (int mt = 0; mt < 4; ++mt)
                ldsm4(a[mt], sA + SWZ128((uint32_t)((warpM * 64 + mt * 16 + lr) * 128 + k16 * 32 + lc)));
            #pragma unroll
            for (int p = 0; p < 2; ++p)
                ldsm4(b[p], sB + SWZ128((uint32_t)((warpN * 32 + p * 16 + lr) * 128 + k16 * 32 + lc)));
            #pragma unroll
            for (int mt = 0; mt < 4; ++mt)
                #pragma unroll
                for (int nt = 0; nt < 4; ++nt)
                    mma_f16(c[mt][nt], a[mt], b[nt >> 1][nt & 1], b[nt >> 1][(nt & 1) + 2]);
        }
        __syncthreads();
        if (kt + 2 < 4) load_stage(st, kt + 2);
    }

    // Stage z for both gates: zstage[gate][128 rows][66]
    {
        int gate = warpN >> 1;
        int njb  = (warpN & 1) * 32;
        #pragma unroll
        for (int mt = 0; mt < 4; ++mt) {
            #pragma unroll
            for (int nt = 0; nt < 4; ++nt) {
                int row = warpM * 64 + mt * 16 + grp;
                int j   = njb + nt * 8 + 2 * lq;
                float2* z0 = (float2*)(smem + ((gate * 128 + row) * 66 + j) * 4);
                float2* z1 = (float2*)(smem + ((gate * 128 + row + 8) * 66 + j) * 4);
                *z0 = make_float2(c[mt][nt][0], c[mt][nt][1]);
                *z1 = make_float2(c[mt][nt][2], c[mt][nt][3]);
            }
        }
    }
    __syncthreads();

    // Fused elementwise + per-segment scan (32 contiguous rows per thread).
    {
        const int s  = tid >> 6;          // segment 0..3
        const int j0 = tid & 63;
        const int d  = head * 256 + jslab * 64 + j0;
        const float bi = __ldg(ig_b + d);
        const float ba = __ldg(ag_b + d);
        const float sp = g_sp[d];
        const float L2E = 1.44269504088896f;
        const float* zs = (const float*)smem;
        const __half* xh = g_xh + (size_t)(m0 + s * 32) * Dd + d;
        float A = 1.f, h = 0.f;
        #pragma unroll 4
        for (int it = 0; it < 32; ++it) {
            int row = s * 32 + it;
            float zi = zs[row * 66 + j0] + bi;
            float za = zs[(128 + row) * 66 + j0] + ba;
            float ei, ea, gx, ga, a, mult;
            asm("ex2.approx.f32 %0, %1;" : "=f"(ei) : "f"(-zi * L2E));
            asm("rcp.approx.f32 %0, %1;" : "=f"(gx) : "f"(1.f + ei));
            asm("ex2.approx.f32 %0, %1;" : "=f"(ea) : "f"(-za * L2E));
            asm("rcp.approx.f32 %0, %1;" : "=f"(ga) : "f"(1.f + ea));
            float la = -8.f * ga * sp;
            asm("ex2.approx.f32 %0, %1;" : "=f"(a) : "f"(la * L2E));
            float m2 = fmaxf(fmaf(-a, a, 1.f), 0.f);
            asm("sqrt.approx.f32 %0, %1;" : "=f"(mult) : "f"(m2));
            float xv = __half2float(xh[(size_t)it * Dd]);
            float nx = xv * gx * mult;
            g_anx[(size_t)(m0 + row) * Dd + d] = make_float2(a, nx);
            h = fmaf(a, h, nx);
            A *= a;
        }
        float2* sseg = (float2*)(smem + OFF_SEG);
        sseg[s * 64 + j0] = make_float2(A, h);
    }
    __syncthreads();
    if (tid < 64) {
        float2* sseg = (float2*)(smem + OFF_SEG);
        float2 s0 = sseg[tid], s1 = sseg[64 + tid], s2 = sseg[128 + tid], s3 = sseg[192 + tid];
        float Ac = s0.x * s1.x * s2.x * s3.x;
        float hc = fmaf(s3.x, fmaf(s2.x, fmaf(s1.x, s0.y, s1.y), s2.y), s3.y);
        int b  = m0 >> 12;
        int ci = (m0 & 4095) >> 7;
        int dd = head * 256 + jslab * 64 + tid;
        g_chunkA[ci * BD + b * Dd + dd] = Ac;
        g_chunkH[ci * BD + b * Dd + dd] = hc;
    }
}

// ---------------------------------------------------------------------------
// Scan phase
// ---------------------------------------------------------------------------
__global__ void scan_part2(const float* __restrict__ hidden, float* __restrict__ hfinal, int write_h)
{
    int ch = blockIdx.x * blockDim.x + threadIdx.x;
    float A[CHUNKS], Hc[CHUNKS];
    #pragma unroll
    for (int ci = 0; ci < CHUNKS; ++ci) {
        A[ci]  = g_chunkA[ci * BD + ch];
        Hc[ci] = g_chunkH[ci * BD + ch];
    }
    float h = hidden[ch];
    #pragma unroll
    for (int ci = 0; ci < CHUNKS; ++ci) {
        g_Hin[ci * BD + ch] = h;
        h = fmaf(A[ci], h, Hc[ci]);
    }
    if (write_h) hfinal[ch] = h;
}

__global__ void scan_part3(float* __restrict__ y)
{
    int g  = blockIdx.x * blockDim.x + threadIdx.x;
    int ci = g / BD;
    int ch = g % BD;
    int b = ch / Dd, d = ch % Dd;
    size_t off = ((size_t)(b * Ll + ci * CLEN)) * Dd + d;
    const float2* p = g_anx + off;
    float* yp = y + off;

    float h = g_Hin[ci * BD + ch];
    float2 cur[8];
    #pragma unroll
    for (int i = 0; i < 8; ++i) cur[i] = p[(size_t)i * Dd];
    #pragma unroll 1
    for (int base = 0; base < CLEN; base += 8) {
        float2 nxt[8];
        if (base + 8 < CLEN) {
            #pragma unroll
            for (int i = 0; i < 8; ++i) nxt[i] = p[(size_t)(base + 8 + i) * Dd];
        } else {
            #pragma unroll
            for (int i = 0; i < 8; ++i) nxt[i] = make_float2(0.f, 0.f);
        }
        #pragma unroll
        for (int i = 0; i < 8; ++i) {
            h = fmaf(cur[i].x, h, cur[i].y);
            yp[(size_t)(base + i) * Dd] = h;
        }
        #pragma unroll
        for (int i = 0; i < 8; ++i) cur[i] = nxt[i];
    }
}

extern "C" void kernel_launch(void* const* d_in, const int* in_sizes, int n_in,
                              void* d_out, int out_size)
{
    const float* x        = (const float*)d_in[0];
    const float* hidden   = (const float*)d_in[1];
    const float* a_param  = (const float*)d_in[2];
    const float* ig_w     = (const float*)d_in[3];
    const float* ig_b     = (const float*)d_in[4];
    const float* ag_w     = (const float*)d_in[5];
    const float* ag_b     = (const float*)d_in[6];
    float* y = (float*)d_out;

    int write_h = (out_size >= BLt * Dd + BD) ? 1 : 0;
    float* hf = y + (size_t)BLt * Dd;

    cudaFuncSetAttribute(gates_kernel, cudaFuncAttributeMaxDynamicSharedMemorySize, SMEM_TOTAL);

    xconv_kernel<<<((size_t)BLt * Dd) / (256 * 8), 256>>>(x);
    prep_kernel<<<1024, 256>>>(ig_w, ag_w, a_param);
    gates_kernel<<<dim3(32, 128), 256, SMEM_TOTAL>>>(ig_b, ag_b);
    scan_part2<<<BD / 256, 256>>>(hidden, hf, write_h);
    scan_part3<<<(BD * CHUNKS) / 256, 256>>>(y);
}